// round 5
// baseline (speedup 1.0000x reference)
#include <cuda_runtime.h>
#include <math.h>

#define Bn 8
#define Cn 64
#define Hn 256
#define Wn 256
#define HWn (Hn*Wn)          // 65536
#define PIXELS (Bn*HWn)      // 524288

typedef unsigned long long ull;

// Scratch for Q, K, V (device global, no alloc)
__device__ float g_qkv[3ULL * Bn * Cn * Hn * Wn];

// ---- f32x2 packed-FMA helpers (sm_103a; exact fp32 per half) ------------
__device__ __forceinline__ ull pk2(float lo, float hi) {
    ull r; asm("mov.b64 %0,{%1,%2};" : "=l"(r) : "f"(lo), "f"(hi)); return r;
}
__device__ __forceinline__ void upk2(ull v, float& lo, float& hi) {
    asm("mov.b64 {%0,%1},%2;" : "=f"(lo), "=f"(hi) : "l"(v));
}
__device__ __forceinline__ void ffma2(ull& d, ull a, ull b) {
    asm("fma.rn.f32x2 %0,%1,%2,%0;" : "+l"(d) : "l"(a), "l"(b));
}
// 16B shared load as two packed f32x2 operands
__device__ __forceinline__ void lds2(ull& a, ull& b, const float* p) {
    unsigned s = (unsigned)__cvta_generic_to_shared(p);
    asm volatile("ld.shared.v2.u64 {%0,%1},[%2];" : "=l"(a), "=l"(b) : "r"(s));
}

// ---------------------------------------------------------------------------
// Kernel 1: QKV projection with f32x2.  One thread per pixel.
// ---------------------------------------------------------------------------
__global__ __launch_bounds__(256, 2)
void qkv_kernel(const float* __restrict__ x,
                const float* __restrict__ Wq, const float* __restrict__ bq,
                const float* __restrict__ Wk, const float* __restrict__ bk,
                const float* __restrict__ Wv, const float* __restrict__ bv)
{
    extern __shared__ float sm1[];
    float* Wsm = sm1;                 // 192 x 64
    float* bsm = sm1 + 192 * 64;      // 192

    const int tid = threadIdx.x;

    for (int idx = tid; idx < 192 * 16; idx += 256) {
        int o  = idx >> 4;
        int k4 = idx & 15;
        const float* src = (o < 64) ? Wq : ((o < 128) ? Wk : Wv);
        int oo = o & 63;
        reinterpret_cast<float4*>(Wsm)[idx] =
            reinterpret_cast<const float4*>(src + oo * 64)[k4];
    }
    if (tid < 192) {
        bsm[tid] = (tid < 64) ? bq[tid] : ((tid < 128) ? bk[tid - 64] : bv[tid - 128]);
    }
    __syncthreads();

    const int p  = blockIdx.x * 256 + tid;
    const int b  = p >> 16;
    const int hw = p & 65535;

    // pack 64 input channels into 32 f32x2 pairs
    ull xp[32];
    const float* xpp = x + (size_t)b * 64 * HWn + hw;
    #pragma unroll
    for (int j = 0; j < 32; j++) {
        float a = xpp[(size_t)(2 * j) * HWn];
        float c = xpp[(size_t)(2 * j + 1) * HWn];
        xp[j] = pk2(a, c);
    }

    #pragma unroll 2
    for (int o = 0; o < 192; o++) {
        ull a0 = 0ull, a1 = 0ull;
        const float* wrow = Wsm + o * 64;
        #pragma unroll
        for (int k2 = 0; k2 < 16; k2++) {
            ull w0, w1;
            lds2(w0, w1, wrow + k2 * 4);
            ffma2(a0, w0, xp[k2 * 2]);
            ffma2(a1, w1, xp[k2 * 2 + 1]);
        }
        float l0, h0, l1, h1;
        upk2(a0, l0, h0); upk2(a1, l1, h1);
        float acc = bsm[o] + ((l0 + h0) + (l1 + h1));
        int proj = o >> 6;
        int oo   = o & 63;
        g_qkv[((size_t)proj * Bn * Cn + (size_t)b * 64 + oo) * HWn + hw] = acc;
    }
}

// ---------------------------------------------------------------------------
// Kernel 2: attention + BN + PReLU.  Block = one (b,c) x 64-row h-tile.
// Threads: 8x32 (ty2=warp 0..7 -> 8 h-rows each; tx2=lane 0..31 -> 8 cols each)
// 8x8 register micro-tile held as 8x4 packed f32x2 accumulators.
// Smem: PsT[256g][68] (P transposed, padded), union(QsT 32x64 + Ks 32x260 /
//       Vs 32x256 / red 512), rowsc[64].
// ---------------------------------------------------------------------------
#define STP 68
#define STK 260
#define PST_FLOATS (256 * STP)                       // 17408
#define UN_FLOATS  (32 * 64 + 32 * STK)              // 10368 (>= Vs 8192, red 512)
#define SMEM_ATTN_FLOATS (PST_FLOATS + UN_FLOATS + 64)

__global__ __launch_bounds__(256, 1)
void attn_kernel(const float* __restrict__ gamma, const float* __restrict__ beta,
                 const float* __restrict__ rmean, const float* __restrict__ rvar,
                 const float* __restrict__ alphap, float* __restrict__ out)
{
    extern __shared__ float sm[];
    float* PsT   = sm;                       // 256 x STP
    float* Un    = sm + PST_FLOATS;          // union region
    float* rowsc = sm + PST_FLOATS + UN_FLOATS;

    float* QsT = Un;                         // 32 x 64   (phase A)
    float* Ks  = Un + 32 * 64;               // 32 x STK  (phase A)
    float* Vs  = Un;                         // 32 x 256  (phase C)
    float* red = Un;                         // 512       (phase B)

    const int tid = threadIdx.x;
    const int ty2 = tid >> 5;                // 0..7
    const int tx2 = tid & 31;                // 0..31
    const int bc  = blockIdx.x >> 2;
    const int ht  = blockIdx.x & 3;
    const int c   = bc & 63;
    const int h0  = ht * 64;

    const float* Qg = g_qkv + (size_t)bc * HWn;
    const float* Kg = g_qkv + (size_t)(512 + bc) * HWn;
    const float* Vg = g_qkv + (size_t)(1024 + bc) * HWn;

    // ================= Phase A: S = Q K^T (64h x 256g), K dim = 256 w ======
    ull acc[8][4];
    #pragma unroll
    for (int i = 0; i < 8; i++)
        #pragma unroll
        for (int j = 0; j < 4; j++) acc[i][j] = 0ull;

    for (int ch = 0; ch < 8; ch++) {
        const int w0 = ch * 32;
        __syncthreads();
        {   // QsT[w_local][h] : 32 x 64
            int h = tid >> 2, wq = tid & 3;
            const float* qrow = Qg + (size_t)(h0 + h) * 256 + w0 + wq * 8;
            float4 v0 = *(const float4*)(qrow);
            float4 v1 = *(const float4*)(qrow + 4);
            int wb = wq * 8;
            QsT[(wb + 0) * 64 + h] = v0.x; QsT[(wb + 1) * 64 + h] = v0.y;
            QsT[(wb + 2) * 64 + h] = v0.z; QsT[(wb + 3) * 64 + h] = v0.w;
            QsT[(wb + 4) * 64 + h] = v1.x; QsT[(wb + 5) * 64 + h] = v1.y;
            QsT[(wb + 6) * 64 + h] = v1.z; QsT[(wb + 7) * 64 + h] = v1.w;
        }
        {   // Ks[w_local][g] : 32 x 256 (stride STK), transposed from gmem
            int g0 = (tid >> 3) * 8, wq = tid & 7;
            float4 r[8];
            #pragma unroll
            for (int r8 = 0; r8 < 8; r8++)
                r[r8] = *(const float4*)(Kg + (size_t)(g0 + r8) * 256 + w0 + wq * 4);
            const float* rf = (const float*)r;
            #pragma unroll
            for (int jj = 0; jj < 4; jj++) {
                float4 s0 = make_float4(rf[0 * 4 + jj], rf[1 * 4 + jj], rf[2 * 4 + jj], rf[3 * 4 + jj]);
                float4 s1 = make_float4(rf[4 * 4 + jj], rf[5 * 4 + jj], rf[6 * 4 + jj], rf[7 * 4 + jj]);
                *(float4*)(Ks + (wq * 4 + jj) * STK + g0)     = s0;
                *(float4*)(Ks + (wq * 4 + jj) * STK + g0 + 4) = s1;
            }
        }
        __syncthreads();
        #pragma unroll 4
        for (int k = 0; k < 32; k++) {
            float af[8];
            *(float4*)(af)     = *(const float4*)(QsT + k * 64 + ty2 * 8);
            *(float4*)(af + 4) = *(const float4*)(QsT + k * 64 + ty2 * 8 + 4);
            ull b0, b1, b2, b3;
            lds2(b0, b1, Ks + k * STK + tx2 * 8);
            lds2(b2, b3, Ks + k * STK + tx2 * 8 + 4);
            #pragma unroll
            for (int i = 0; i < 8; i++) {
                ull ad = pk2(af[i], af[i]);
                ffma2(acc[i][0], ad, b0); ffma2(acc[i][1], ad, b1);
                ffma2(acc[i][2], ad, b2); ffma2(acc[i][3], ad, b3);
            }
        }
    }

    // store S*0.25 transposed -> PsT[g][h]
    #pragma unroll
    for (int jp = 0; jp < 4; jp++) {
        float cl[8], dh[8];
        #pragma unroll
        for (int i = 0; i < 8; i++) upk2(acc[i][jp], cl[i], dh[i]);
        int g1 = tx2 * 8 + jp * 2;
        float* p1 = PsT + g1 * STP + ty2 * 8;
        float* p2 = PsT + (g1 + 1) * STP + ty2 * 8;
        *(float4*)(p1)     = make_float4(cl[0]*0.25f, cl[1]*0.25f, cl[2]*0.25f, cl[3]*0.25f);
        *(float4*)(p1 + 4) = make_float4(cl[4]*0.25f, cl[5]*0.25f, cl[6]*0.25f, cl[7]*0.25f);
        *(float4*)(p2)     = make_float4(dh[0]*0.25f, dh[1]*0.25f, dh[2]*0.25f, dh[3]*0.25f);
        *(float4*)(p2 + 4) = make_float4(dh[4]*0.25f, dh[5]*0.25f, dh[6]*0.25f, dh[7]*0.25f);
    }
    __syncthreads();

    // ================= Phase B: softmax over g (partial reduction) =========
    {
        const int h = tid & 63, q = tid >> 6;
        float m = -1e30f;
        #pragma unroll 8
        for (int i = 0; i < 64; i++) m = fmaxf(m, PsT[(q * 64 + i) * STP + h]);
        red[q * 64 + h] = m;
        __syncthreads();
        float M = fmaxf(fmaxf(red[h], red[64 + h]), fmaxf(red[128 + h], red[192 + h]));
        float s = 0.f;
        #pragma unroll 8
        for (int i = 0; i < 64; i++) {
            float* p = &PsT[(q * 64 + i) * STP + h];
            float e = __expf(*p - M);
            *p = e; s += e;
        }
        __syncthreads();       // all M reads done before red reuse
        red[256 + q * 64 + h] = s;
    }
    __syncthreads();
    if (tid < 64)
        rowsc[tid] = 1.f / (red[256 + tid] + red[320 + tid] + red[384 + tid] + red[448 + tid]);

    // ================= Phase C: out = P * V (64h x 256w), K dim = 256 g ====
    ull oacc[8][4];
    #pragma unroll
    for (int i = 0; i < 8; i++)
        #pragma unroll
        for (int j = 0; j < 4; j++) oacc[i][j] = 0ull;

    for (int ch = 0; ch < 8; ch++) {
        const int g0c = ch * 32;
        __syncthreads();
        {   // Vs[g_local][w] : 32 x 256, natural layout
            int gl = tid >> 3, wq = tid & 7;
            const float* vrow = Vg + (size_t)(g0c + gl) * 256;
            #pragma unroll
            for (int ii = 0; ii < 8; ii++) {
                int w = ii * 32 + wq * 4;
                *(float4*)(Vs + gl * 256 + w) = *(const float4*)(vrow + w);
            }
        }
        __syncthreads();
        #pragma unroll 4
        for (int k = 0; k < 32; k++) {
            float af[8];
            const float* prow = PsT + (g0c + k) * STP + ty2 * 8;
            *(float4*)(af)     = *(const float4*)(prow);
            *(float4*)(af + 4) = *(const float4*)(prow + 4);
            ull b0, b1, b2, b3;
            lds2(b0, b1, Vs + k * 256 + tx2 * 8);
            lds2(b2, b3, Vs + k * 256 + tx2 * 8 + 4);
            #pragma unroll
            for (int i = 0; i < 8; i++) {
                ull ad = pk2(af[i], af[i]);
                ffma2(oacc[i][0], ad, b0); ffma2(oacc[i][1], ad, b1);
                ffma2(oacc[i][2], ad, b2); ffma2(oacc[i][3], ad, b3);
            }
        }
    }

    // ================= Epilogue: 1/sum, BN(eval), PReLU, store =============
    const float inv = gamma[c] * rsqrtf(rvar[c] + 1e-5f);
    const float sh  = beta[c] - rmean[c] * inv;
    const float al  = alphap[0];
    #pragma unroll
    for (int i = 0; i < 8; i++) {
        float rs = rowsc[ty2 * 8 + i] * inv;
        float o[8];
        #pragma unroll
        for (int jp = 0; jp < 4; jp++) upk2(oacc[i][jp], o[2 * jp], o[2 * jp + 1]);
        #pragma unroll
        for (int j = 0; j < 8; j++) {
            float v = o[j] * rs + sh;
            o[j] = (v >= 0.f) ? v : al * v;
        }
        float* op = out + (size_t)bc * HWn + (size_t)(h0 + ty2 * 8 + i) * 256 + tx2 * 8;
        *(float4*)(op)     = make_float4(o[0], o[1], o[2], o[3]);
        *(float4*)(op + 4) = make_float4(o[4], o[5], o[6], o[7]);
    }
}

// ---------------------------------------------------------------------------
extern "C" void kernel_launch(void* const* d_in, const int* in_sizes, int n_in,
                              void* d_out, int out_size)
{
    (void)in_sizes; (void)n_in; (void)out_size;
    const float* x     = (const float*)d_in[0];
    const float* Wq    = (const float*)d_in[1];
    const float* bq    = (const float*)d_in[2];
    const float* Wk    = (const float*)d_in[3];
    const float* bk    = (const float*)d_in[4];
    const float* Wv    = (const float*)d_in[5];
    const float* bv    = (const float*)d_in[6];
    const float* gamma = (const float*)d_in[7];
    const float* beta  = (const float*)d_in[8];
    const float* rmean = (const float*)d_in[9];
    const float* rvar  = (const float*)d_in[10];
    const float* alpha = (const float*)d_in[11];
    float* out = (float*)d_out;

    const int smem1 = (192 * 64 + 192) * sizeof(float);
    const int smem2 = SMEM_ATTN_FLOATS * sizeof(float);   // 111,360 B
    cudaFuncSetAttribute(qkv_kernel,  cudaFuncAttributeMaxDynamicSharedMemorySize, smem1);
    cudaFuncSetAttribute(attn_kernel, cudaFuncAttributeMaxDynamicSharedMemorySize, smem2);

    qkv_kernel<<<PIXELS / 256, 256, smem1>>>(x, Wq, bq, Wk, bk, Wv, bv);
    attn_kernel<<<Bn * Cn * 4, 256, smem2>>>(gamma, beta, rmean, rvar, alpha, out);
}

// round 7
// speedup vs baseline: 1.9545x; 1.9545x over previous
#include <cuda_runtime.h>
#include <math.h>

typedef unsigned int u32;
typedef unsigned long long u64;

#define Bn 8
#define HWn 65536
#define NBC 512
#define PIXELS (Bn*HWn)

// Q,K,V scratch (fp32), layout [proj][b*64+c][h*256+w]
__device__ float g_qkv[3ULL * NBC * HWn];

// ---------------- FFMA2 helpers (qkv kernel) -------------------------------
__device__ __forceinline__ u64 pk2(float lo, float hi) {
    u64 r; asm("mov.b64 %0,{%1,%2};" : "=l"(r) : "f"(lo), "f"(hi)); return r;
}
__device__ __forceinline__ void upk2(u64 v, float& lo, float& hi) {
    asm("mov.b64 {%0,%1},%2;" : "=f"(lo), "=f"(hi) : "l"(v));
}
__device__ __forceinline__ void ffma2(u64& d, u64 a, u64 b) {
    asm("fma.rn.f32x2 %0,%1,%2,%0;" : "+l"(d) : "l"(a), "l"(b));
}
__device__ __forceinline__ void lds2(u64& a, u64& b, const float* p) {
    unsigned s = (unsigned)__cvta_generic_to_shared(p);
    asm volatile("ld.shared.v2.u64 {%0,%1},[%2];" : "=l"(a), "=l"(b) : "r"(s));
}

// ---------------- tf32 mma helpers -----------------------------------------
__device__ __forceinline__ u32 cvt_tf32(float f) {
    u32 r; asm("cvt.rna.tf32.f32 %0,%1;" : "=r"(r) : "f"(f)); return r;
}
__device__ __forceinline__ void mma8(float* c, u32 a0, u32 a1, u32 a2, u32 a3,
                                     u32 b0, u32 b1) {
    asm("mma.sync.aligned.m16n8k8.row.col.f32.tf32.tf32.f32 "
        "{%0,%1,%2,%3},{%4,%5,%6,%7},{%8,%9},{%0,%1,%2,%3};"
        : "+f"(c[0]), "+f"(c[1]), "+f"(c[2]), "+f"(c[3])
        : "r"(a0), "r"(a1), "r"(a2), "r"(a3), "r"(b0), "r"(b1));
}

// ---------------------------------------------------------------------------
// Kernel 1: QKV projection (FFMA2). Q scaled x0.25 (folds attention 1/scale).
// ---------------------------------------------------------------------------
__global__ __launch_bounds__(256, 2)
void qkv_kernel(const float* __restrict__ x,
                const float* __restrict__ Wq, const float* __restrict__ bq,
                const float* __restrict__ Wk, const float* __restrict__ bk,
                const float* __restrict__ Wv, const float* __restrict__ bv)
{
    extern __shared__ float sm1[];
    float* Wsm = sm1;
    float* bsm = sm1 + 192 * 64;

    const int tid = threadIdx.x;
    for (int idx = tid; idx < 192 * 16; idx += 256) {
        int o = idx >> 4, k4 = idx & 15;
        const float* src = (o < 64) ? Wq : ((o < 128) ? Wk : Wv);
        reinterpret_cast<float4*>(Wsm)[idx] =
            reinterpret_cast<const float4*>(src + (o & 63) * 64)[k4];
    }
    if (tid < 192)
        bsm[tid] = (tid < 64) ? bq[tid] : ((tid < 128) ? bk[tid - 64] : bv[tid - 128]);
    __syncthreads();

    const int p  = blockIdx.x * 256 + tid;
    const int b  = p >> 16;
    const int hw = p & 65535;

    u64 xp[32];
    const float* xpp = x + (size_t)b * 64 * HWn + hw;
    #pragma unroll
    for (int j = 0; j < 32; j++)
        xp[j] = pk2(xpp[(size_t)(2 * j) * HWn], xpp[(size_t)(2 * j + 1) * HWn]);

    #pragma unroll 2
    for (int o = 0; o < 192; o++) {
        u64 a0 = 0ull, a1 = 0ull;
        const float* wrow = Wsm + o * 64;
        #pragma unroll
        for (int k2 = 0; k2 < 16; k2++) {
            u64 w0, w1;
            lds2(w0, w1, wrow + k2 * 4);
            ffma2(a0, w0, xp[k2 * 2]);
            ffma2(a1, w1, xp[k2 * 2 + 1]);
        }
        float l0, h0, l1, h1;
        upk2(a0, l0, h0); upk2(a1, l1, h1);
        float acc = bsm[o] + ((l0 + h0) + (l1 + h1));
        int proj = o >> 6, oo = o & 63;
        if (proj == 0) acc *= 0.25f;   // S/scale folded into Q (exact: 2^-2)
        g_qkv[((size_t)proj * NBC + (size_t)(b * 64 + oo)) * HWn + hw] = acc;
    }
}

// ---------------------------------------------------------------------------
// Kernel 2: attention via mma.sync tf32 + softmax + BN + PReLU.
// CTA = (b,c) x 128-row h-tile. 8 warps as 2m x 4n; warp tile 64x64.
// ---------------------------------------------------------------------------
#define PS_STRIDE 260
#define KS_STRIDE 73
#define PS_FLOATS  (128 * PS_STRIDE)               // 33280
#define VST_FLOATS (256 * KS_STRIDE)               // 18688
#define OFF_RED    (PS_FLOATS + VST_FLOATS)        // 51968 (floats)
#define OFF_ROWSC  (OFF_RED + 1024)                // 52992
#define SMEM_ATTN_FLOATS (OFF_ROWSC + 128)         // 53120 -> 212480 B

__global__ __launch_bounds__(256, 1)
void attn_kernel(const float* __restrict__ gamma, const float* __restrict__ beta,
                 const float* __restrict__ rmean, const float* __restrict__ rvar,
                 const float* __restrict__ alphap, float* __restrict__ out)
{
    extern __shared__ float sm[];
    float* Ps    = sm;                     // 128 x 260 (phase B/C)
    float* Qs    = sm;                     // 128 x 73  (phase A, aliases Ps)
    float* Ks    = sm + 128 * KS_STRIDE;   // 256 x 73  (phase A, aliases Ps)
    float* VsT   = sm + PS_FLOATS;         // 256 x 73  (phase C)
    float* redm  = sm + OFF_RED;           // 128 x 4
    float* reds  = redm + 512;             // 128 x 4
    float* rowsc = sm + OFF_ROWSC;         // 128

    const int tid  = threadIdx.x;
    const int lane = tid & 31;
    const int wid  = tid >> 5;
    const int wm   = (wid & 1) * 64;       // warp m offset (0/64)
    const int wn   = (wid >> 1) * 64;      // warp n offset (0/64/128/192)
    const int lr   = lane >> 2;            // 0..7
    const int lc   = lane & 3;             // 0..3

    const int bc = blockIdx.x >> 1;
    const int h0 = (blockIdx.x & 1) * 128;
    const int c  = bc & 63;

    const float* Qg = g_qkv + (size_t)bc * HWn + (size_t)h0 * 256;
    const float* Kg = g_qkv + (size_t)(NBC + bc) * HWn;
    const float* Vg = g_qkv + (size_t)(2 * NBC + bc) * HWn;

    float acc[4][8][4];
    #pragma unroll
    for (int i = 0; i < 4; i++)
        #pragma unroll
        for (int j = 0; j < 8; j++)
            #pragma unroll
            for (int k = 0; k < 4; k++) acc[i][j][k] = 0.f;

    // ===== Phase A: S = Q . K^T  (128 x 256, k=256 in 4 chunks of 64) ======
    for (int kc = 0; kc < 4; kc++) {
        __syncthreads();
        #pragma unroll
        for (int i = 0; i < 8; i++) {        // Qs: 128 rows x 64
            int id = tid + 256 * i;
            int r = id >> 4, c4 = (id & 15) * 4;
            float4 v = *(const float4*)(Qg + (size_t)r * 256 + kc * 64 + c4);
            float* d = Qs + r * KS_STRIDE + c4;
            d[0] = v.x; d[1] = v.y; d[2] = v.z; d[3] = v.w;
        }
        #pragma unroll
        for (int i = 0; i < 16; i++) {       // Ks: 256 rows x 64
            int id = tid + 256 * i;
            int r = id >> 4, c4 = (id & 15) * 4;
            float4 v = *(const float4*)(Kg + (size_t)r * 256 + kc * 64 + c4);
            float* d = Ks + r * KS_STRIDE + c4;
            d[0] = v.x; d[1] = v.y; d[2] = v.z; d[3] = v.w;
        }
        __syncthreads();
        #pragma unroll 2
        for (int kk = 0; kk < 8; kk++) {
            const int kb = kk * 8;
            u32 af[4][4];
            #pragma unroll
            for (int ms = 0; ms < 4; ms++) {
                const float* q = Qs + (wm + ms * 16 + lr) * KS_STRIDE + kb + lc;
                af[ms][0] = cvt_tf32(q[0]);
                af[ms][1] = cvt_tf32(q[8 * KS_STRIDE]);
                af[ms][2] = cvt_tf32(q[4]);
                af[ms][3] = cvt_tf32(q[8 * KS_STRIDE + 4]);
            }
            #pragma unroll
            for (int ns = 0; ns < 8; ns++) {
                const float* kp = Ks + (wn + ns * 8 + lr) * KS_STRIDE + kb + lc;
                u32 b0 = cvt_tf32(kp[0]);
                u32 b1 = cvt_tf32(kp[4]);
                #pragma unroll
                for (int ms = 0; ms < 4; ms++)
                    mma8(acc[ms][ns], af[ms][0], af[ms][1], af[ms][2], af[ms][3], b0, b1);
            }
        }
    }

    // ===== Phase B: softmax over n (rows of 256) ===========================
    #pragma unroll
    for (int ms = 0; ms < 4; ms++)
        #pragma unroll
        for (int half = 0; half < 2; half++) {
            float m = -1e30f;
            #pragma unroll
            for (int ns = 0; ns < 8; ns++)
                m = fmaxf(m, fmaxf(acc[ms][ns][half * 2], acc[ms][ns][half * 2 + 1]));
            m = fmaxf(m, __shfl_xor_sync(0xffffffffu, m, 1));
            m = fmaxf(m, __shfl_xor_sync(0xffffffffu, m, 2));
            if (lc == 0) redm[(wm + ms * 16 + lr + half * 8) * 4 + (wid >> 1)] = m;
        }
    __syncthreads();
    #pragma unroll
    for (int ms = 0; ms < 4; ms++)
        #pragma unroll
        for (int half = 0; half < 2; half++) {
            int row = wm + ms * 16 + lr + half * 8;
            const float* rm = redm + row * 4;
            float M = fmaxf(fmaxf(rm[0], rm[1]), fmaxf(rm[2], rm[3]));
            float s = 0.f;
            #pragma unroll
            for (int ns = 0; ns < 8; ns++) {
                float e0 = __expf(acc[ms][ns][half * 2]     - M);
                float e1 = __expf(acc[ms][ns][half * 2 + 1] - M);
                s += e0 + e1;
                *(float2*)(Ps + row * PS_STRIDE + wn + ns * 8 + 2 * lc) = make_float2(e0, e1);
            }
            s += __shfl_xor_sync(0xffffffffu, s, 1);
            s += __shfl_xor_sync(0xffffffffu, s, 2);
            if (lc == 0) reds[row * 4 + (wid >> 1)] = s;
        }
    __syncthreads();
    if (tid < 128)
        rowsc[tid] = 1.f / (reds[tid * 4] + reds[tid * 4 + 1] + reds[tid * 4 + 2] + reds[tid * 4 + 3]);

    // ===== Phase C: out = P . V  (k=256 g in 4 chunks of 64) ===============
    #pragma unroll
    for (int i = 0; i < 4; i++)
        #pragma unroll
        for (int j = 0; j < 8; j++)
            #pragma unroll
            for (int k = 0; k < 4; k++) acc[i][j][k] = 0.f;

    for (int gc = 0; gc < 4; gc++) {
        __syncthreads();
        #pragma unroll
        for (int i = 0; i < 16; i++) {   // VsT[w][g_local]: transpose on the fly
            int id = tid + 256 * i;
            int gl = id >> 6, w4 = (id & 63) * 4;
            float4 v = *(const float4*)(Vg + (size_t)(gc * 64 + gl) * 256 + w4);
            VsT[(w4 + 0) * KS_STRIDE + gl] = v.x;
            VsT[(w4 + 1) * KS_STRIDE + gl] = v.y;
            VsT[(w4 + 2) * KS_STRIDE + gl] = v.z;
            VsT[(w4 + 3) * KS_STRIDE + gl] = v.w;
        }
        __syncthreads();
        #pragma unroll 2
        for (int kk = 0; kk < 8; kk++) {
            const int kb = kk * 8;
            u32 af[4][4];
            #pragma unroll
            for (int ms = 0; ms < 4; ms++) {
                const float* p = Ps + (wm + ms * 16 + lr) * PS_STRIDE + gc * 64 + kb + lc;
                af[ms][0] = cvt_tf32(p[0]);
                af[ms][1] = cvt_tf32(p[8 * PS_STRIDE]);
                af[ms][2] = cvt_tf32(p[4]);
                af[ms][3] = cvt_tf32(p[8 * PS_STRIDE + 4]);
            }
            #pragma unroll
            for (int ns = 0; ns < 8; ns++) {
                const float* vp = VsT + (wn + ns * 8 + lr) * KS_STRIDE + kb + lc;
                u32 b0 = cvt_tf32(vp[0]);
                u32 b1 = cvt_tf32(vp[4]);
                #pragma unroll
                for (int ms = 0; ms < 4; ms++)
                    mma8(acc[ms][ns], af[ms][0], af[ms][1], af[ms][2], af[ms][3], b0, b1);
            }
        }
    }

    // ===== Epilogue: 1/sum, BN(eval), PReLU, store =========================
    const float inv = gamma[c] * rsqrtf(rvar[c] + 1e-5f);
    const float sh  = beta[c] - rmean[c] * inv;
    const float al  = alphap[0];
    #pragma unroll
    for (int ms = 0; ms < 4; ms++)
        #pragma unroll
        for (int half = 0; half < 2; half++) {
            int row = wm + ms * 16 + lr + half * 8;
            float rs = rowsc[row] * inv;
            float* op = out + (size_t)bc * HWn + (size_t)(h0 + row) * 256;
            #pragma unroll
            for (int ns = 0; ns < 8; ns++) {
                float v0 = acc[ms][ns][half * 2]     * rs + sh;
                float v1 = acc[ms][ns][half * 2 + 1] * rs + sh;
                v0 = (v0 >= 0.f) ? v0 : al * v0;
                v1 = (v1 >= 0.f) ? v1 : al * v1;
                *(float2*)(op + wn + ns * 8 + 2 * lc) = make_float2(v0, v1);
            }
        }
}

// ---------------------------------------------------------------------------
extern "C" void kernel_launch(void* const* d_in, const int* in_sizes, int n_in,
                              void* d_out, int out_size)
{
    (void)in_sizes; (void)n_in; (void)out_size;
    const float* x     = (const float*)d_in[0];
    const float* Wq    = (const float*)d_in[1];
    const float* bq    = (const float*)d_in[2];
    const float* Wk    = (const float*)d_in[3];
    const float* bk    = (const float*)d_in[4];
    const float* Wv    = (const float*)d_in[5];
    const float* bv    = (const float*)d_in[6];
    const float* gamma = (const float*)d_in[7];
    const float* beta  = (const float*)d_in[8];
    const float* rmean = (const float*)d_in[9];
    const float* rvar  = (const float*)d_in[10];
    const float* alpha = (const float*)d_in[11];
    float* out = (float*)d_out;

    const int smem1 = (192 * 64 + 192) * sizeof(float);
    const int smem2 = SMEM_ATTN_FLOATS * sizeof(float);   // 212,480 B
    cudaFuncSetAttribute(qkv_kernel,  cudaFuncAttributeMaxDynamicSharedMemorySize, smem1);
    cudaFuncSetAttribute(attn_kernel, cudaFuncAttributeMaxDynamicSharedMemorySize, smem2);

    qkv_kernel<<<PIXELS / 256, 256, smem1>>>(x, Wq, bq, Wk, bk, Wv, bv);
    attn_kernel<<<NBC * 2, 256, smem2>>>(gamma, beta, rmean, rvar, alpha, out);
}

// round 8
// speedup vs baseline: 2.0799x; 1.0642x over previous
#include <cuda_runtime.h>
#include <math.h>

typedef unsigned int u32;
typedef unsigned long long u64;

#define HWn 65536
#define NBC 512

// Q,K,V scratch (fp32, tf32-prerounded), layout [proj][b*64+c][h*256+w]
__device__ float g_qkv[3ULL * NBC * HWn];

// ---------------- tf32 mma helpers -----------------------------------------
__device__ __forceinline__ u32 cvt_tf32(float f) {
    u32 r; asm("cvt.rna.tf32.f32 %0,%1;" : "=r"(r) : "f"(f)); return r;
}
__device__ __forceinline__ u32 fau(float f) { return __float_as_uint(f); }
__device__ __forceinline__ void mma8(float* c, u32 a0, u32 a1, u32 a2, u32 a3,
                                     u32 b0, u32 b1) {
    asm("mma.sync.aligned.m16n8k8.row.col.f32.tf32.tf32.f32 "
        "{%0,%1,%2,%3},{%4,%5,%6,%7},{%8,%9},{%0,%1,%2,%3};"
        : "+f"(c[0]), "+f"(c[1]), "+f"(c[2]), "+f"(c[3])
        : "r"(a0), "r"(a1), "r"(a2), "r"(a3), "r"(b0), "r"(b1));
}

// ---------------------------------------------------------------------------
// Kernel 1: QKV projection via split-tf32 MMA (near-exact: residual ~2^-22).
// CTA = 128 pixels x 192 outputs, k=64. 8 warps as 2m x 4n, warp tile 64x48.
// Epilogue stores Q(x0.25)/K/V pre-rounded to tf32 for the attention kernel.
// ---------------------------------------------------------------------------
#define WS 68
#define A_H 0
#define A_L (128*WS)
#define W_H (2*128*WS)
#define W_L (2*128*WS + 192*WS)
#define B_OFF (2*128*WS + 2*192*WS)
#define SMEM_QKV ((B_OFF + 192) * 4)          // 174,848 B

__global__ __launch_bounds__(256, 1)
void qkv_mma(const float* __restrict__ x,
             const float* __restrict__ Wq, const float* __restrict__ bq,
             const float* __restrict__ Wk, const float* __restrict__ bk,
             const float* __restrict__ Wv, const float* __restrict__ bv)
{
    extern __shared__ float sq[];
    const int tid  = threadIdx.x;
    const int lane = tid & 31;
    const int wid  = tid >> 5;
    const int lr   = lane >> 2;
    const int lc   = lane & 3;
    const int wm   = (wid & 1) * 64;
    const int wn   = (wid >> 1) * 48;

    const int p0  = blockIdx.x * 128;
    const int b   = p0 >> 16;
    const int hw0 = p0 & 65535;

    // ---- W load + split ----
    for (int idx = tid; idx < 192 * 64; idx += 256) {
        int o = idx >> 6, k = idx & 63;
        const float* src = (o < 64) ? Wq : ((o < 128) ? Wk : Wv);
        float w  = src[(o & 63) * 64 + k];
        float wh = __uint_as_float(cvt_tf32(w));
        sq[W_H + o * WS + k] = wh;
        sq[W_L + o * WS + k] = w - wh;
    }
    if (tid < 192)
        sq[B_OFF + tid] = (tid < 64) ? bq[tid] : ((tid < 128) ? bk[tid - 64] : bv[tid - 128]);

    // ---- x tile load + split (64 ch x 128 hw, coalesced) ----
    const float* xb = x + (size_t)b * 64 * HWn + hw0;
    #pragma unroll
    for (int i2 = 0; i2 < 32; i2++) {
        int idx = tid + 256 * i2;
        int hw = idx & 127, i = idx >> 7;
        float v  = xb[(size_t)i * HWn + hw];
        float vh = __uint_as_float(cvt_tf32(v));
        sq[A_H + hw * WS + i] = vh;
        sq[A_L + hw * WS + i] = v - vh;
    }
    __syncthreads();

    float acc[4][6][4];
    #pragma unroll
    for (int i = 0; i < 4; i++)
        #pragma unroll
        for (int j = 0; j < 6; j++)
            #pragma unroll
            for (int k = 0; k < 4; k++) acc[i][j][k] = 0.f;

    #pragma unroll 2
    for (int kk = 0; kk < 8; kk++) {
        const int kb = kk * 8;
        u32 ah[4][4], al[4][4];
        #pragma unroll
        for (int ms = 0; ms < 4; ms++) {
            const float* ph = sq + A_H + (wm + ms * 16 + lr) * WS + kb + lc;
            const float* pl = sq + A_L + (wm + ms * 16 + lr) * WS + kb + lc;
            ah[ms][0] = fau(ph[0]); ah[ms][1] = fau(ph[8 * WS]);
            ah[ms][2] = fau(ph[4]); ah[ms][3] = fau(ph[8 * WS + 4]);
            al[ms][0] = fau(pl[0]); al[ms][1] = fau(pl[8 * WS]);
            al[ms][2] = fau(pl[4]); al[ms][3] = fau(pl[8 * WS + 4]);
        }
        #pragma unroll
        for (int ns = 0; ns < 6; ns++) {
            const float* bh = sq + W_H + (wn + ns * 8 + lr) * WS + kb + lc;
            const float* bl = sq + W_L + (wn + ns * 8 + lr) * WS + kb + lc;
            u32 b0h = fau(bh[0]), b1h = fau(bh[4]);
            u32 b0l = fau(bl[0]), b1l = fau(bl[4]);
            #pragma unroll
            for (int ms = 0; ms < 4; ms++) {
                mma8(acc[ms][ns], ah[ms][0], ah[ms][1], ah[ms][2], ah[ms][3], b0h, b1h);
                mma8(acc[ms][ns], ah[ms][0], ah[ms][1], ah[ms][2], ah[ms][3], b0l, b1l);
                mma8(acc[ms][ns], al[ms][0], al[ms][1], al[ms][2], al[ms][3], b0h, b1h);
            }
        }
    }

    // ---- epilogue: +bias, Q x0.25, pre-round to tf32, scatter-store ----
    #pragma unroll
    for (int ms = 0; ms < 4; ms++) {
        int r0 = wm + ms * 16 + lr;
        #pragma unroll
        for (int ns = 0; ns < 6; ns++) {
            int n0 = wn + ns * 8 + 2 * lc;
            #pragma unroll
            for (int q = 0; q < 4; q++) {
                int o = n0 + (q & 1);
                int r = r0 + (q >> 1) * 8;
                float v = acc[ms][ns][q] + sq[B_OFF + o];
                int proj = o >> 6;
                if (proj == 0) v *= 0.25f;     // fold attention 1/scale
                g_qkv[((size_t)proj * NBC + (size_t)(b * 64 + (o & 63))) * HWn + hw0 + r]
                    = __uint_as_float(cvt_tf32(v));
            }
        }
    }
}

// ---------------------------------------------------------------------------
// Kernel 2: attention via mma.sync tf32 (operands pre-rounded) + softmax
// (no max-subtraction; |S| <~ 8) + BN + PReLU.
// CTA = (b,c) x 128-row h-tile. 8 warps as 2m x 4n; warp tile 64x64.
// ---------------------------------------------------------------------------
#define PS_STRIDE 260
#define QK_STRIDE 68
#define VT_STRIDE 73
#define PS_FLOATS  (128 * PS_STRIDE)               // 33280 (aliases Qs+Ks 26112)
#define VST_FLOATS (256 * VT_STRIDE)               // 18688
#define OFF_RED    (PS_FLOATS + VST_FLOATS)        // 51968
#define OFF_ROWSC  (OFF_RED + 512)
#define SMEM_ATTN_FLOATS (OFF_ROWSC + 128)         // 52608 -> 210,432 B

__global__ __launch_bounds__(256, 1)
void attn_kernel(const float* __restrict__ gamma, const float* __restrict__ beta,
                 const float* __restrict__ rmean, const float* __restrict__ rvar,
                 const float* __restrict__ alphap, float* __restrict__ out)
{
    extern __shared__ float sm[];
    float* Ps    = sm;                      // 128 x 260 (phase B/C)
    float* Qs    = sm;                      // 128 x 68  (phase A, aliases Ps)
    float* Ks    = sm + 128 * QK_STRIDE;    // 256 x 68  (phase A, aliases Ps)
    float* VsT   = sm + PS_FLOATS;          // 256 x 73  (phase C)
    float* reds  = sm + OFF_RED;            // 128 x 4
    float* rowsc = sm + OFF_ROWSC;          // 128

    const int tid  = threadIdx.x;
    const int lane = tid & 31;
    const int wid  = tid >> 5;
    const int wm   = (wid & 1) * 64;
    const int wn   = (wid >> 1) * 64;
    const int lr   = lane >> 2;
    const int lc   = lane & 3;

    const int bc = blockIdx.x >> 1;
    const int h0 = (blockIdx.x & 1) * 128;
    const int c  = bc & 63;

    const float* Qg = g_qkv + (size_t)bc * HWn + (size_t)h0 * 256;
    const float* Kg = g_qkv + (size_t)(NBC + bc) * HWn;
    const float* Vg = g_qkv + (size_t)(2 * NBC + bc) * HWn;

    float acc[4][8][4];
    #pragma unroll
    for (int i = 0; i < 4; i++)
        #pragma unroll
        for (int j = 0; j < 8; j++)
            #pragma unroll
            for (int k = 0; k < 4; k++) acc[i][j][k] = 0.f;

    // ===== Phase A: S = Q . K^T  (128 x 256, k=256 in 4 chunks of 64) ======
    for (int kc = 0; kc < 4; kc++) {
        __syncthreads();
        #pragma unroll
        for (int i = 0; i < 8; i++) {        // Qs: 128 rows x 64
            int id = tid + 256 * i;
            int r = id >> 4, c4 = (id & 15) * 4;
            float4 v = *(const float4*)(Qg + (size_t)r * 256 + kc * 64 + c4);
            float* d = Qs + r * QK_STRIDE + c4;
            d[0] = v.x; d[1] = v.y; d[2] = v.z; d[3] = v.w;
        }
        #pragma unroll
        for (int i = 0; i < 16; i++) {       // Ks: 256 rows x 64
            int id = tid + 256 * i;
            int r = id >> 4, c4 = (id & 15) * 4;
            float4 v = *(const float4*)(Kg + (size_t)r * 256 + kc * 64 + c4);
            float* d = Ks + r * QK_STRIDE + c4;
            d[0] = v.x; d[1] = v.y; d[2] = v.z; d[3] = v.w;
        }
        __syncthreads();
        #pragma unroll 2
        for (int kk = 0; kk < 8; kk++) {
            const int kb = kk * 8;
            u32 af[4][4];
            #pragma unroll
            for (int ms = 0; ms < 4; ms++) {
                const float* q = Qs + (wm + ms * 16 + lr) * QK_STRIDE + kb + lc;
                af[ms][0] = fau(q[0]);
                af[ms][1] = fau(q[8 * QK_STRIDE]);
                af[ms][2] = fau(q[4]);
                af[ms][3] = fau(q[8 * QK_STRIDE + 4]);
            }
            #pragma unroll
            for (int ns = 0; ns < 8; ns++) {
                const float* kp = Ks + (wn + ns * 8 + lr) * QK_STRIDE + kb + lc;
                u32 b0 = fau(kp[0]);
                u32 b1 = fau(kp[4]);
                #pragma unroll
                for (int ms = 0; ms < 4; ms++)
                    mma8(acc[ms][ns], af[ms][0], af[ms][1], af[ms][2], af[ms][3], b0, b1);
            }
        }
    }

    // ===== Phase B: softmax over n (no max-sub; exp safe, |S|<~8) ==========
    __syncthreads();   // all Phase A fragment reads done before Ps overwrite
    #pragma unroll
    for (int ms = 0; ms < 4; ms++)
        #pragma unroll
        for (int half = 0; half < 2; half++) {
            int row = wm + ms * 16 + lr + half * 8;
            float s = 0.f;
            #pragma unroll
            for (int ns = 0; ns < 8; ns++) {
                float e0 = __expf(acc[ms][ns][half * 2]);
                float e1 = __expf(acc[ms][ns][half * 2 + 1]);
                s += e0 + e1;
                *(float2*)(Ps + row * PS_STRIDE + wn + ns * 8 + 2 * lc) =
                    make_float2(__uint_as_float(cvt_tf32(e0)),
                                __uint_as_float(cvt_tf32(e1)));
            }
            s += __shfl_xor_sync(0xffffffffu, s, 1);
            s += __shfl_xor_sync(0xffffffffu, s, 2);
            if (lc == 0) reds[row * 4 + (wid >> 1)] = s;
        }
    __syncthreads();
    if (tid < 128)
        rowsc[tid] = 1.f / (reds[tid * 4] + reds[tid * 4 + 1] + reds[tid * 4 + 2] + reds[tid * 4 + 3]);

    // ===== Phase C: out = P . V  (k=256 g in 4 chunks of 64) ===============
    #pragma unroll
    for (int i = 0; i < 4; i++)
        #pragma unroll
        for (int j = 0; j < 8; j++)
            #pragma unroll
            for (int k = 0; k < 4; k++) acc[i][j][k] = 0.f;

    for (int gc = 0; gc < 4; gc++) {
        __syncthreads();
        #pragma unroll
        for (int i = 0; i < 16; i++) {   // VsT[w][g_local]: transpose on the fly
            int id = tid + 256 * i;
            int gl = id >> 6, w4 = (id & 63) * 4;
            float4 v = *(const float4*)(Vg + (size_t)(gc * 64 + gl) * 256 + w4);
            VsT[(w4 + 0) * VT_STRIDE + gl] = v.x;
            VsT[(w4 + 1) * VT_STRIDE + gl] = v.y;
            VsT[(w4 + 2) * VT_STRIDE + gl] = v.z;
            VsT[(w4 + 3) * VT_STRIDE + gl] = v.w;
        }
        __syncthreads();
        #pragma unroll 2
        for (int kk = 0; kk < 8; kk++) {
            const int kb = kk * 8;
            u32 af[4][4];
            #pragma unroll
            for (int ms = 0; ms < 4; ms++) {
                const float* p = Ps + (wm + ms * 16 + lr) * PS_STRIDE + gc * 64 + kb + lc;
                af[ms][0] = fau(p[0]);
                af[ms][1] = fau(p[8 * PS_STRIDE]);
                af[ms][2] = fau(p[4]);
                af[ms][3] = fau(p[8 * PS_STRIDE + 4]);
            }
            #pragma unroll
            for (int ns = 0; ns < 8; ns++) {
                const float* vp = VsT + (wn + ns * 8 + lr) * VT_STRIDE + kb + lc;
                u32 b0 = fau(vp[0]);
                u32 b1 = fau(vp[4]);
                #pragma unroll
                for (int ms = 0; ms < 4; ms++)
                    mma8(acc[ms][ns], af[ms][0], af[ms][1], af[ms][2], af[ms][3], b0, b1);
            }
        }
    }

    // ===== Epilogue: 1/sum, BN(eval), PReLU, store =========================
    const float inv = gamma[c] * rsqrtf(rvar[c] + 1e-5f);
    const float sh  = beta[c] - rmean[c] * inv;
    const float al  = alphap[0];
    #pragma unroll
    for (int ms = 0; ms < 4; ms++)
        #pragma unroll
        for (int half = 0; half < 2; half++) {
            int row = wm + ms * 16 + lr + half * 8;
            float rs = rowsc[row] * inv;
            float* op = out + (size_t)bc * HWn + (size_t)(h0 + row) * 256;
            #pragma unroll
            for (int ns = 0; ns < 8; ns++) {
                float v0 = acc[ms][ns][half * 2]     * rs + sh;
                float v1 = acc[ms][ns][half * 2 + 1] * rs + sh;
                v0 = (v0 >= 0.f) ? v0 : al * v0;
                v1 = (v1 >= 0.f) ? v1 : al * v1;
                *(float2*)(op + wn + ns * 8 + 2 * lc) = make_float2(v0, v1);
            }
        }
}

// ---------------------------------------------------------------------------
extern "C" void kernel_launch(void* const* d_in, const int* in_sizes, int n_in,
                              void* d_out, int out_size)
{
    (void)in_sizes; (void)n_in; (void)out_size;
    const float* x     = (const float*)d_in[0];
    const float* Wq    = (const float*)d_in[1];
    const float* bq    = (const float*)d_in[2];
    const float* Wk    = (const float*)d_in[3];
    const float* bk    = (const float*)d_in[4];
    const float* Wv    = (const float*)d_in[5];
    const float* bv    = (const float*)d_in[6];
    const float* gamma = (const float*)d_in[7];
    const float* beta  = (const float*)d_in[8];
    const float* rmean = (const float*)d_in[9];
    const float* rvar  = (const float*)d_in[10];
    const float* alpha = (const float*)d_in[11];
    float* out = (float*)d_out;

    const int smem2 = SMEM_ATTN_FLOATS * sizeof(float);
    cudaFuncSetAttribute(qkv_mma,     cudaFuncAttributeMaxDynamicSharedMemorySize, SMEM_QKV);
    cudaFuncSetAttribute(attn_kernel, cudaFuncAttributeMaxDynamicSharedMemorySize, smem2);

    qkv_mma<<<4096, 256, SMEM_QKV>>>(x, Wq, bq, Wk, bk, Wv, bv);
    attn_kernel<<<NBC * 2, 256, smem2>>>(gamma, beta, rmean, rvar, alpha, out);
}

// round 9
// speedup vs baseline: 2.8713x; 1.3805x over previous
#include <cuda_runtime.h>
#include <math.h>

typedef unsigned int u32;
typedef unsigned long long u64;

#define HWn 65536
#define NBC 512

// Q,K,V scratch (fp32, tf32-prerounded), layout [proj][b*64+c][h*256+w]
__device__ float g_qkv[3ULL * NBC * HWn];

// ---------------- helpers ---------------------------------------------------
__device__ __forceinline__ u32 s2u(const void* p) { return (u32)__cvta_generic_to_shared(p); }
__device__ __forceinline__ u32 cvt_tf32(float f) {
    u32 r; asm("cvt.rna.tf32.f32 %0,%1;" : "=r"(r) : "f"(f)); return r;
}
__device__ __forceinline__ u32 fau(float f) { return __float_as_uint(f); }
__device__ __forceinline__ float uaf(u32 u) { return __uint_as_float(u); }
__device__ __forceinline__ void mma8(float* c, u32 a0, u32 a1, u32 a2, u32 a3,
                                     u32 b0, u32 b1) {
    asm("mma.sync.aligned.m16n8k8.row.col.f32.tf32.tf32.f32 "
        "{%0,%1,%2,%3},{%4,%5,%6,%7},{%8,%9},{%0,%1,%2,%3};"
        : "+f"(c[0]), "+f"(c[1]), "+f"(c[2]), "+f"(c[3])
        : "r"(a0), "r"(a1), "r"(a2), "r"(a3), "r"(b0), "r"(b1));
}
__device__ __forceinline__ void cpa16(u32 smem, const float* g) {
    asm volatile("cp.async.cg.shared.global [%0],[%1],16;" :: "r"(smem), "l"(g));
}
#define CPA_COMMIT() asm volatile("cp.async.commit_group;" ::: "memory")
#define CPA_WAIT0()  asm volatile("cp.async.wait_group 0;" ::: "memory")

// ---------------------------------------------------------------------------
// Kernel 1: QKV projection, persistent CTAs. W loaded once (tf32-rounded);
// x tiles cp.async double-buffered; x split to (hi,lo) tf32 in a smem pass;
// 2-term MMA (ah*wh + al*wh). Q scaled x0.25. Outputs pre-rounded to tf32.
// ---------------------------------------------------------------------------
#define T_PER 4
#define XRS 136                               // x plane stride (floats)
#define QW   0                                // W hi: 192 x 68
#define QB   (192*68)                         // bias 192
#define QAH  (QB + 192)                       // Ah: 64 x 136
#define QAL  (QAH + 64*XRS)                   // Al: 64 x 136
#define QRAW (QAL + 64*XRS)                   // raw: 2 x 64 x 136
#define SMEM_QKV_FLOATS (QRAW + 2*64*XRS)     // 48064 -> 192,256 B

__global__ __launch_bounds__(256, 1)
void qkv_mma(const float* __restrict__ x,
             const float* __restrict__ Wq, const float* __restrict__ bq,
             const float* __restrict__ Wk, const float* __restrict__ bk,
             const float* __restrict__ Wv, const float* __restrict__ bv)
{
    extern __shared__ float sq[];
    const int tid  = threadIdx.x;
    const int lane = tid & 31;
    const int wid  = tid >> 5;
    const int lr   = lane >> 2;
    const int lc   = lane & 3;
    const int wm   = (wid & 1) * 64;
    const int wn   = (wid >> 1) * 48;

    // ---- W load once (tf32-rounded) + bias ----
    for (int idx = tid; idx < 192 * 64; idx += 256) {
        int o = idx >> 6, k = idx & 63;
        const float* src = (o < 64) ? Wq : ((o < 128) ? Wk : Wv);
        sq[QW + o * 68 + k] = uaf(cvt_tf32(src[(o & 63) * 64 + k]));
    }
    if (tid < 192)
        sq[QB + tid] = (tid < 64) ? bq[tid] : ((tid < 128) ? bk[tid - 64] : bv[tid - 128]);

    // ---- issue x tile j into raw[j&1] ----
    auto issueX = [&](int j) {
        int p0  = (blockIdx.x * T_PER + j) * 128;
        int b   = p0 >> 16;
        int hw0 = p0 & 65535;
        const float* xb = x + (size_t)b * 64 * HWn + hw0;
        u32 dst = s2u(sq + QRAW + (j & 1) * 64 * XRS);
        #pragma unroll
        for (int i = 0; i < 8; i++) {
            int idx = tid + 256 * i;
            int ch = idx >> 5, seg = idx & 31;
            cpa16(dst + (u32)(ch * XRS + seg * 4) * 4, xb + (size_t)ch * HWn + seg * 4);
        }
    };

    issueX(0); CPA_COMMIT();

    for (int j = 0; j < T_PER; j++) {
        CPA_WAIT0();
        __syncthreads();
        if (j + 1 < T_PER) { issueX(j + 1); CPA_COMMIT(); }

        // ---- split pass: raw -> Ah/Al (both tf32-rounded) ----
        {
            const float* raw = sq + QRAW + (j & 1) * 64 * XRS;
            #pragma unroll
            for (int i = 0; i < 8; i++) {
                int idx = tid + 256 * i;
                int ch = idx >> 5, seg = idx & 31;
                float4 v = *(const float4*)(raw + ch * XRS + seg * 4);
                float4 h, l;
                h.x = uaf(cvt_tf32(v.x)); l.x = uaf(cvt_tf32(v.x - h.x));
                h.y = uaf(cvt_tf32(v.y)); l.y = uaf(cvt_tf32(v.y - h.y));
                h.z = uaf(cvt_tf32(v.z)); l.z = uaf(cvt_tf32(v.z - h.z));
                h.w = uaf(cvt_tf32(v.w)); l.w = uaf(cvt_tf32(v.w - h.w));
                *(float4*)(sq + QAH + ch * XRS + seg * 4) = h;
                *(float4*)(sq + QAL + ch * XRS + seg * 4) = l;
            }
        }
        __syncthreads();

        // ---- MMA: [128 pix] x [192 out], k=64, 2 terms ----
        float acc[4][6][4];
        #pragma unroll
        for (int i = 0; i < 4; i++)
            #pragma unroll
            for (int jj = 0; jj < 6; jj++)
                #pragma unroll
                for (int q = 0; q < 4; q++) acc[i][jj][q] = 0.f;

        #pragma unroll 2
        for (int kk = 0; kk < 8; kk++) {
            const int kb = kk * 8;
            u32 ah[4][4], al[4][4];
            #pragma unroll
            for (int ms = 0; ms < 4; ms++) {
                int r = wm + ms * 16 + lr;
                const float* ph = sq + QAH + (kb + lc) * XRS + r;
                const float* pl = sq + QAL + (kb + lc) * XRS + r;
                ah[ms][0] = fau(ph[0]); ah[ms][1] = fau(ph[8]);
                ah[ms][2] = fau(ph[4 * XRS]); ah[ms][3] = fau(ph[4 * XRS + 8]);
                al[ms][0] = fau(pl[0]); al[ms][1] = fau(pl[8]);
                al[ms][2] = fau(pl[4 * XRS]); al[ms][3] = fau(pl[4 * XRS + 8]);
            }
            #pragma unroll
            for (int ns = 0; ns < 6; ns++) {
                const float* wp = sq + QW + (wn + ns * 8 + lr) * 68 + kb + lc;
                u32 b0 = fau(wp[0]), b1 = fau(wp[4]);
                #pragma unroll
                for (int ms = 0; ms < 4; ms++) {
                    mma8(acc[ms][ns], ah[ms][0], ah[ms][1], ah[ms][2], ah[ms][3], b0, b1);
                    mma8(acc[ms][ns], al[ms][0], al[ms][1], al[ms][2], al[ms][3], b0, b1);
                }
            }
        }

        // ---- epilogue: +bias, Q x0.25, tf32 pre-round, store ----
        int p0  = (blockIdx.x * T_PER + j) * 128;
        int b   = p0 >> 16;
        int hw0 = p0 & 65535;
        #pragma unroll
        for (int ms = 0; ms < 4; ms++) {
            int r0 = wm + ms * 16 + lr;
            #pragma unroll
            for (int ns = 0; ns < 6; ns++) {
                int n0 = wn + ns * 8 + 2 * lc;
                #pragma unroll
                for (int q = 0; q < 4; q++) {
                    int o = n0 + (q & 1);
                    int r = r0 + (q >> 1) * 8;
                    float v = acc[ms][ns][q] + sq[QB + o];
                    int proj = o >> 6;
                    if (proj == 0) v *= 0.25f;
                    g_qkv[((size_t)proj * NBC + (size_t)(b * 64 + (o & 63))) * HWn + hw0 + r]
                        = uaf(cvt_tf32(v));
                }
            }
        }
    }
}

// ---------------------------------------------------------------------------
// Kernel 2: attention tf32 mma.sync; Phase A cp.async double-buffered (k=32
// chunks); softmax without max-subtraction; BN + PReLU fused.
// CTA = (b,c) x 128-row h-tile. 8 warps as 2m x 4n; warp tile 64x64.
// ---------------------------------------------------------------------------
#define PS_STRIDE 260
#define AB_STRIDE 36
#define AB_FLOATS (128*AB_STRIDE + 256*AB_STRIDE)  // 13824 per buffer
#define VT_STRIDE 73
#define PS_FLOATS  (128 * PS_STRIDE)               // 33280 (>= 2*13824)
#define VST_FLOATS (256 * VT_STRIDE)
#define OFF_RED    (PS_FLOATS + VST_FLOATS)
#define OFF_ROWSC  (OFF_RED + 512)
#define SMEM_ATTN_FLOATS (OFF_ROWSC + 128)         // 52608 -> 210,432 B

__global__ __launch_bounds__(256, 1)
void attn_kernel(const float* __restrict__ gamma, const float* __restrict__ beta,
                 const float* __restrict__ rmean, const float* __restrict__ rvar,
                 const float* __restrict__ alphap, float* __restrict__ out)
{
    extern __shared__ float sm[];
    float* Ps    = sm;                      // 128 x 260 (aliases phase-A bufs)
    float* VsT   = sm + PS_FLOATS;          // 256 x 73
    float* reds  = sm + OFF_RED;
    float* rowsc = sm + OFF_ROWSC;

    const int tid  = threadIdx.x;
    const int lane = tid & 31;
    const int wid  = tid >> 5;
    const int wm   = (wid & 1) * 64;
    const int wn   = (wid >> 1) * 64;
    const int lr   = lane >> 2;
    const int lc   = lane & 3;

    const int bc = blockIdx.x >> 1;
    const int h0 = (blockIdx.x & 1) * 128;
    const int c  = bc & 63;

    const float* Qg = g_qkv + (size_t)bc * HWn + (size_t)h0 * 256;
    const float* Kg = g_qkv + (size_t)(NBC + bc) * HWn;
    const float* Vg = g_qkv + (size_t)(2 * NBC + bc) * HWn;

    float acc[4][8][4];
    #pragma unroll
    for (int i = 0; i < 4; i++)
        #pragma unroll
        for (int j = 0; j < 8; j++)
            #pragma unroll
            for (int k = 0; k < 4; k++) acc[i][j][k] = 0.f;

    // ===== Phase A: S = Q . K^T, k=256 in 8 cp.async-pipelined chunks of 32 =
    auto issueA = [&](int kc) {
        u32 d = s2u(sm + (kc & 1) * AB_FLOATS);
        const float* sq2 = Qg + kc * 32;
        const float* sk2 = Kg + kc * 32;
        #pragma unroll
        for (int i = 0; i < 12; i++) {
            int idx = tid + 256 * i;
            if (idx < 1024) {
                int r = idx >> 3, seg = idx & 7;
                cpa16(d + (u32)(r * AB_STRIDE + seg * 4) * 4, sq2 + (size_t)r * 256 + seg * 4);
            } else {
                int i2 = idx - 1024;
                int r = i2 >> 3, seg = i2 & 7;
                cpa16(d + (u32)(128 * AB_STRIDE + r * AB_STRIDE + seg * 4) * 4,
                      sk2 + (size_t)r * 256 + seg * 4);
            }
        }
    };

    issueA(0); CPA_COMMIT();
    for (int kc = 0; kc < 8; kc++) {
        CPA_WAIT0();
        __syncthreads();
        if (kc + 1 < 8) { issueA(kc + 1); CPA_COMMIT(); }
        const float* bufQ = sm + (kc & 1) * AB_FLOATS;
        const float* bufK = bufQ + 128 * AB_STRIDE;
        #pragma unroll
        for (int kk = 0; kk < 4; kk++) {
            const int kb = kk * 8;
            u32 af[4][4];
            #pragma unroll
            for (int ms = 0; ms < 4; ms++) {
                const float* q = bufQ + (wm + ms * 16 + lr) * AB_STRIDE + kb + lc;
                af[ms][0] = fau(q[0]);
                af[ms][1] = fau(q[8 * AB_STRIDE]);
                af[ms][2] = fau(q[4]);
                af[ms][3] = fau(q[8 * AB_STRIDE + 4]);
            }
            #pragma unroll
            for (int ns = 0; ns < 8; ns++) {
                const float* kp = bufK + (wn + ns * 8 + lr) * AB_STRIDE + kb + lc;
                u32 b0 = fau(kp[0]);
                u32 b1 = fau(kp[4]);
                #pragma unroll
                for (int ms = 0; ms < 4; ms++)
                    mma8(acc[ms][ns], af[ms][0], af[ms][1], af[ms][2], af[ms][3], b0, b1);
            }
        }
    }

    // ===== Phase B: softmax over n (no max-sub; |S| <~ 8) ==================
    __syncthreads();
    #pragma unroll
    for (int ms = 0; ms < 4; ms++)
        #pragma unroll
        for (int half = 0; half < 2; half++) {
            int row = wm + ms * 16 + lr + half * 8;
            float s = 0.f;
            #pragma unroll
            for (int ns = 0; ns < 8; ns++) {
                float e0 = __expf(acc[ms][ns][half * 2]);
                float e1 = __expf(acc[ms][ns][half * 2 + 1]);
                s += e0 + e1;
                *(float2*)(Ps + row * PS_STRIDE + wn + ns * 8 + 2 * lc) =
                    make_float2(uaf(cvt_tf32(e0)), uaf(cvt_tf32(e1)));
            }
            s += __shfl_xor_sync(0xffffffffu, s, 1);
            s += __shfl_xor_sync(0xffffffffu, s, 2);
            if (lc == 0) reds[row * 4 + (wid >> 1)] = s;
        }
    __syncthreads();
    if (tid < 128)
        rowsc[tid] = 1.f / (reds[tid * 4] + reds[tid * 4 + 1] + reds[tid * 4 + 2] + reds[tid * 4 + 3]);

    // ===== Phase C: out = P . V  (k=256 g in 4 chunks of 64) ===============
    #pragma unroll
    for (int i = 0; i < 4; i++)
        #pragma unroll
        for (int j = 0; j < 8; j++)
            #pragma unroll
            for (int k = 0; k < 4; k++) acc[i][j][k] = 0.f;

    for (int gc = 0; gc < 4; gc++) {
        __syncthreads();
        #pragma unroll
        for (int i = 0; i < 16; i++) {   // VsT[w][g_local]: transpose on the fly
            int id = tid + 256 * i;
            int gl = id >> 6, w4 = (id & 63) * 4;
            float4 v = *(const float4*)(Vg + (size_t)(gc * 64 + gl) * 256 + w4);
            VsT[(w4 + 0) * VT_STRIDE + gl] = v.x;
            VsT[(w4 + 1) * VT_STRIDE + gl] = v.y;
            VsT[(w4 + 2) * VT_STRIDE + gl] = v.z;
            VsT[(w4 + 3) * VT_STRIDE + gl] = v.w;
        }
        __syncthreads();
        #pragma unroll 2
        for (int kk = 0; kk < 8; kk++) {
            const int kb = kk * 8;
            u32 af[4][4];
            #pragma unroll
            for (int ms = 0; ms < 4; ms++) {
                const float* p = Ps + (wm + ms * 16 + lr) * PS_STRIDE + gc * 64 + kb + lc;
                af[ms][0] = fau(p[0]);
                af[ms][1] = fau(p[8 * PS_STRIDE]);
                af[ms][2] = fau(p[4]);
                af[ms][3] = fau(p[8 * PS_STRIDE + 4]);
            }
            #pragma unroll
            for (int ns = 0; ns < 8; ns++) {
                const float* vp = VsT + (wn + ns * 8 + lr) * VT_STRIDE + kb + lc;
                u32 b0 = fau(vp[0]);
                u32 b1 = fau(vp[4]);
                #pragma unroll
                for (int ms = 0; ms < 4; ms++)
                    mma8(acc[ms][ns], af[ms][0], af[ms][1], af[ms][2], af[ms][3], b0, b1);
            }
        }
    }

    // ===== Epilogue: 1/sum, BN(eval), PReLU, store =========================
    const float inv = gamma[c] * rsqrtf(rvar[c] + 1e-5f);
    const float sh  = beta[c] - rmean[c] * inv;
    const float al  = alphap[0];
    #pragma unroll
    for (int ms = 0; ms < 4; ms++)
        #pragma unroll
        for (int half = 0; half < 2; half++) {
            int row = wm + ms * 16 + lr + half * 8;
            float rs = rowsc[row] * inv;
            float* op = out + (size_t)bc * HWn + (size_t)(h0 + row) * 256;
            #pragma unroll
            for (int ns = 0; ns < 8; ns++) {
                float v0 = acc[ms][ns][half * 2]     * rs + sh;
                float v1 = acc[ms][ns][half * 2 + 1] * rs + sh;
                v0 = (v0 >= 0.f) ? v0 : al * v0;
                v1 = (v1 >= 0.f) ? v1 : al * v1;
                *(float2*)(op + wn + ns * 8 + 2 * lc) = make_float2(v0, v1);
            }
        }
}

// ---------------------------------------------------------------------------
extern "C" void kernel_launch(void* const* d_in, const int* in_sizes, int n_in,
                              void* d_out, int out_size)
{
    (void)in_sizes; (void)n_in; (void)out_size;
    const float* x     = (const float*)d_in[0];
    const float* Wq    = (const float*)d_in[1];
    const float* bq    = (const float*)d_in[2];
    const float* Wk    = (const float*)d_in[3];
    const float* bk    = (const float*)d_in[4];
    const float* Wv    = (const float*)d_in[5];
    const float* bv    = (const float*)d_in[6];
    const float* gamma = (const float*)d_in[7];
    const float* beta  = (const float*)d_in[8];
    const float* rmean = (const float*)d_in[9];
    const float* rvar  = (const float*)d_in[10];
    const float* alpha = (const float*)d_in[11];
    float* out = (float*)d_out;

    const int smem1 = SMEM_QKV_FLOATS * sizeof(float);    // 192,256 B
    const int smem2 = SMEM_ATTN_FLOATS * sizeof(float);   // 210,432 B
    cudaFuncSetAttribute(qkv_mma,     cudaFuncAttributeMaxDynamicSharedMemorySize, smem1);
    cudaFuncSetAttribute(attn_kernel, cudaFuncAttributeMaxDynamicSharedMemorySize, smem2);

    qkv_mma<<<1024, 256, smem1>>>(x, Wq, bq, Wk, bk, Wv, bv);
    attn_kernel<<<NBC * 2, 256, smem2>>>(gamma, beta, rmean, rvar, alpha, out);
}